// round 5
// baseline (speedup 1.0000x reference)
#include <cuda_runtime.h>
#include <cuda_bf16.h>
#include <cstdint>
#include <math.h>

#define T_TOK 2176
#define HS    2048
#define NQKV  3072
#define NH    16
#define NKV   4
#define HD    128
#define MMETA 128
#define WWIN  512
#define SCALE_F 0.08838834764831845f
#define NEGV  -1.0e30f

// ---------------------------------------------------------------------------
// scratch buffers
// ---------------------------------------------------------------------------
__device__ float g_qkv[T_TOK * NQKV];                    // Q roped+scaled fp32 (K/V cols unused)
__device__ __nv_bfloat16 g_Ahi[T_TOK * HS];
__device__ __nv_bfloat16 g_Alo[T_TOK * HS];
__device__ __nv_bfloat16 g_Bthi[NQKV * HS];              // W transposed [n][k]
__device__ __nv_bfloat16 g_Btlo[NQKV * HS];
__device__ __nv_bfloat16 g_Khi[T_TOK * NKV * HD];        // roped K split
__device__ __nv_bfloat16 g_Klo[T_TOK * NKV * HD];
__device__ __nv_bfloat16 g_Vhi[T_TOK * NKV * HD];
__device__ __nv_bfloat16 g_Vlo[T_TOK * NKV * HD];
__device__ float g_invfreq[64];

__device__ __forceinline__ uint32_t smem_to_u32(const void* p) {
    uint32_t a;
    asm("{ .reg .u64 t; cvta.to.shared.u64 t, %1; cvt.u32.u64 %0, t; }" : "=r"(a) : "l"(p));
    return a;
}
__device__ __forceinline__ uint32_t cvt_bf16x2(float hi, float lo) {
    uint32_t d;
    asm("cvt.rn.bf16x2.f32 %0, %1, %2;" : "=r"(d) : "f"(hi), "f"(lo));
    return d;
}
__device__ __forceinline__ void ldsm_x4(uint32_t* r, uint32_t addr) {
    asm volatile("ldmatrix.sync.aligned.m8n8.x4.shared.b16 {%0,%1,%2,%3}, [%4];"
                 : "=r"(r[0]), "=r"(r[1]), "=r"(r[2]), "=r"(r[3]) : "r"(addr));
}
__device__ __forceinline__ void ldsm_x4t(uint32_t* r, uint32_t addr) {
    asm volatile("ldmatrix.sync.aligned.m8n8.x4.trans.shared.b16 {%0,%1,%2,%3}, [%4];"
                 : "=r"(r[0]), "=r"(r[1]), "=r"(r[2]), "=r"(r[3]) : "r"(addr));
}
__device__ __forceinline__ void ldsm_x2(uint32_t* r, uint32_t addr) {
    asm volatile("ldmatrix.sync.aligned.m8n8.x2.shared.b16 {%0,%1}, [%2];"
                 : "=r"(r[0]), "=r"(r[1]) : "r"(addr));
}
__device__ __forceinline__ void mma_bf16(float* c, const uint32_t* a, const uint32_t* b) {
    asm volatile(
        "mma.sync.aligned.m16n8k16.row.col.f32.bf16.bf16.f32 "
        "{%0,%1,%2,%3}, {%4,%5,%6,%7}, {%8,%9}, {%0,%1,%2,%3};"
        : "+f"(c[0]), "+f"(c[1]), "+f"(c[2]), "+f"(c[3])
        : "r"(a[0]), "r"(a[1]), "r"(a[2]), "r"(a[3]), "r"(b[0]), "r"(b[1]));
}
__device__ __forceinline__ void cp_async16(uint32_t dst, const void* src) {
    asm volatile("cp.async.ca.shared.global [%0], [%1], 16;" :: "r"(dst), "l"(src) : "memory");
}
#define CP_COMMIT() asm volatile("cp.async.commit_group;" ::: "memory")
#define CP_WAIT1()  asm volatile("cp.async.wait_group 1;" ::: "memory")

// ---------------------------------------------------------------------------
// Stage -1: inv_freq table (matches jax fp32 pow to ~1 ulp via double)
// ---------------------------------------------------------------------------
__global__ void init_invfreq_kernel() {
    int i = threadIdx.x;
    g_invfreq[i] = (float)exp(-(double)(2 * i) * (1.0 / 128.0) * log(10000.0));
}

// ---------------------------------------------------------------------------
// Stage 0a: split hidden_states fp32 -> bf16 hi/lo
// ---------------------------------------------------------------------------
__global__ void split_a_kernel(const float* __restrict__ A) {
    int i = (blockIdx.x * blockDim.x + threadIdx.x) * 4;
    if (i >= T_TOK * HS) return;
    float4 v = *(const float4*)&A[i];
    __nv_bfloat16 h0 = __float2bfloat16(v.x);
    __nv_bfloat16 h1 = __float2bfloat16(v.y);
    __nv_bfloat16 h2 = __float2bfloat16(v.z);
    __nv_bfloat16 h3 = __float2bfloat16(v.w);
    __nv_bfloat162 hi01, hi23, lo01, lo23;
    hi01.x = h0; hi01.y = h1; hi23.x = h2; hi23.y = h3;
    lo01.x = __float2bfloat16(v.x - __bfloat162float(h0));
    lo01.y = __float2bfloat16(v.y - __bfloat162float(h1));
    lo23.x = __float2bfloat16(v.z - __bfloat162float(h2));
    lo23.y = __float2bfloat16(v.w - __bfloat162float(h3));
    *(__nv_bfloat162*)&g_Ahi[i]     = hi01;
    *(__nv_bfloat162*)&g_Ahi[i + 2] = hi23;
    *(__nv_bfloat162*)&g_Alo[i]     = lo01;
    *(__nv_bfloat162*)&g_Alo[i + 2] = lo23;
}

// ---------------------------------------------------------------------------
// Stage 0b: transpose + split W[2048,3072] -> Bt_hi/lo[3072][2048]
// ---------------------------------------------------------------------------
__global__ void split_w_kernel(const float* __restrict__ W) {
    __shared__ float tile[32][33];
    int n0 = blockIdx.x * 32;
    int k0 = blockIdx.y * 32;
    int tx = threadIdx.x;
    int ty = threadIdx.y;
#pragma unroll
    for (int p = 0; p < 4; ++p) {
        int k = ty + p * 8;
        tile[k][tx] = W[(size_t)(k0 + k) * NQKV + n0 + tx];
    }
    __syncthreads();
#pragma unroll
    for (int p = 0; p < 4; ++p) {
        int n = ty + p * 8;
        float v = tile[tx][n];
        __nv_bfloat16 hi = __float2bfloat16(v);
        __nv_bfloat16 lo = __float2bfloat16(v - __bfloat162float(hi));
        size_t o = (size_t)(n0 + n) * HS + k0 + tx;
        g_Bthi[o] = hi;
        g_Btlo[o] = lo;
    }
}

// ---------------------------------------------------------------------------
// Stage 1: bf16x3 GEMM (mma.sync), CTA 64x128, warp tile 32x32, BK=32,
// 2-stage cp.async; fused epilogue: bias + RoPE + Q-scale + K/V split.
// One CTA = 64 tokens x 1 head.  Grid (24 heads, 34 token-tiles) = 816 CTAs.
// ---------------------------------------------------------------------------
#define BK 32
#define A_T_B 5120                    // 64 rows * 80B
#define B_T_B 10240                   // 128 rows * 80B
#define STG_B 30720
#define GEMM_SMEM 61440

__global__ __launch_bounds__(256, 2)
void qkv_mma_kernel(const float* __restrict__ bias, const int* __restrict__ pos) {
    extern __shared__ char smem[];
    const uint32_t sb = smem_to_u32(smem);
    const int tid  = threadIdx.x;
    const int wid  = tid >> 5;
    const int lane = tid & 31;
    const int head = blockIdx.x;          // 0..23
    const int bm = blockIdx.y * 64;
    const int bn = head * 128;
    const int wm = (wid >> 2) * 32;       // 0 or 32
    const int wn = (wid & 3) * 32;        // 0,32,64,96

    const __nv_bfloat16* Ahi = g_Ahi + (size_t)bm * HS;
    const __nv_bfloat16* Alo = g_Alo + (size_t)bm * HS;
    const __nv_bfloat16* Bhi = g_Bthi + (size_t)bn * HS;
    const __nv_bfloat16* Blo = g_Btlo + (size_t)bn * HS;

    auto issue_stage = [&](int c, int s) {
#pragma unroll
        for (int q = 0; q < 6; ++q) {
            int idx = q * 256 + tid;                // 0..1535
            const __nv_bfloat16* src;
            uint32_t dst;
            if (idx < 512) {                        // A tiles (64 rows each)
                int arr = idx >> 8;
                int rem = idx & 255;
                int row = rem >> 2, seg = rem & 3;
                src = (arr ? Alo : Ahi) + (size_t)row * HS + c * BK + seg * 8;
                dst = sb + s * STG_B + arr * A_T_B + row * 80 + seg * 16;
            } else {                                // B tiles (128 rows each)
                int arr = (idx - 512) >> 9;
                int rem = idx & 511;
                int row = rem >> 2, seg = rem & 3;
                src = (arr ? Blo : Bhi) + (size_t)row * HS + c * BK + seg * 8;
                dst = sb + s * STG_B + 2 * A_T_B + arr * B_T_B + row * 80 + seg * 16;
            }
            cp_async16(dst, src);
        }
    };

    float acc[2][4][4];
#pragma unroll
    for (int i = 0; i < 2; ++i)
#pragma unroll
        for (int j = 0; j < 4; ++j)
#pragma unroll
            for (int q = 0; q < 4; ++q) acc[i][j][q] = 0.f;

    issue_stage(0, 0); CP_COMMIT();
    issue_stage(1, 1); CP_COMMIT();

    const int acolh = (lane >> 4) << 3;
    const int bcolh = ((lane >> 3) & 1) << 3;
    const int arow  = wm + (lane & 15);
    const int brow  = wn + (lane & 7);

    const int NCH = HS / BK;    // 64
    for (int c = 0; c < NCH; ++c) {
        CP_WAIT1();
        __syncthreads();
        const uint32_t base = sb + (c & 1) * STG_B;
        const uint32_t abase = base + arow * 80;
        const uint32_t bbase = base + 2 * A_T_B + brow * 80;

#pragma unroll
        for (int ks = 0; ks < 2; ++ks) {
            uint32_t ahi[2][4], alo[2][4];
#pragma unroll
            for (int i = 0; i < 2; ++i) {
                uint32_t a = abase + i * (16 * 80) + (acolh + ks * 16) * 2;
                ldsm_x4(ahi[i], a);
                ldsm_x4(alo[i], a + A_T_B);
            }
#pragma unroll
            for (int j = 0; j < 4; ++j) {
                uint32_t bh[2], bl[2];
                uint32_t a = bbase + j * (8 * 80) + (bcolh + ks * 16) * 2;
                ldsm_x2(bh, a);
                ldsm_x2(bl, a + B_T_B);
#pragma unroll
                for (int i = 0; i < 2; ++i) {
                    mma_bf16(acc[i][j], ahi[i], bh);
                    mma_bf16(acc[i][j], ahi[i], bl);
                    mma_bf16(acc[i][j], alo[i], bh);
                }
            }
        }
        __syncthreads();
        if (c + 2 < NCH) issue_stage(c + 2, c & 1);
        CP_COMMIT();
    }

    // ---- fused epilogue: stage to smem, then bias already added ----
    __syncthreads();
    float* Ct = (float*)smem;                 // [64][132] fp32 = 33792 B
    const int r  = lane >> 2;
    const int cc = (lane & 3) * 2;
#pragma unroll
    for (int i = 0; i < 2; ++i) {
#pragma unroll
        for (int j = 0; j < 4; ++j) {
            int col = wn + j * 8 + cc;
            float b0 = bias[bn + col], b1 = bias[bn + col + 1];
            int row = wm + i * 16 + r;
            Ct[row * 132 + col]           = acc[i][j][0] + b0;
            Ct[row * 132 + col + 1]       = acc[i][j][1] + b1;
            Ct[(row + 8) * 132 + col]     = acc[i][j][2] + b0;
            Ct[(row + 8) * 132 + col + 1] = acc[i][j][3] + b1;
        }
    }
    __syncthreads();

    // ---- rope / scale / split per head type ----
#pragma unroll
    for (int p = 0; p < 16; ++p) {
        int idx = p * 256 + tid;        // 4096 = 64 rows x 64 pairs
        int row = idx >> 6;
        int i   = idx & 63;
        int t   = bm + row;
        float x1 = Ct[row * 132 + i];
        float x2 = Ct[row * 132 + i + 64];
        if (head < 20) {
            float ang = (float)pos[t] * g_invfreq[i];
            float c = cosf(ang), s = sinf(ang);
            float y1 = x1 * c - x2 * s;
            float y2 = x2 * c + x1 * s;
            if (head < 16) {
                g_qkv[(size_t)t * NQKV + head * HD + i]      = y1 * SCALE_F;
                g_qkv[(size_t)t * NQKV + head * HD + i + 64] = y2 * SCALE_F;
            } else {
                size_t o = (size_t)t * (NKV * HD) + (head - 16) * HD + i;
                __nv_bfloat16 h1 = __float2bfloat16(y1);
                __nv_bfloat16 h2 = __float2bfloat16(y2);
                g_Khi[o]      = h1;
                g_Khi[o + 64] = h2;
                g_Klo[o]      = __float2bfloat16(y1 - __bfloat162float(h1));
                g_Klo[o + 64] = __float2bfloat16(y2 - __bfloat162float(h2));
            }
        } else {
            size_t o = (size_t)t * (NKV * HD) + (head - 20) * HD + i;
            __nv_bfloat16 h1 = __float2bfloat16(x1);
            __nv_bfloat16 h2 = __float2bfloat16(x2);
            g_Vhi[o]      = h1;
            g_Vhi[o + 64] = h2;
            g_Vlo[o]      = __float2bfloat16(x1 - __bfloat162float(h1));
            g_Vlo[o + 64] = __float2bfloat16(x2 - __bfloat162float(h2));
        }
    }
}

// ---------------------------------------------------------------------------
// Stage 3: attention via mma.sync, split precision, 2 heads per CTA (R4).
// ---------------------------------------------------------------------------
#define APITCH 272
#define ARR_B  (64 * APITCH)
#define ASTAGE (4 * ARR_B)
#define ATTN_SMEM (2 * ASTAGE)

__global__ __launch_bounds__(256, 1)
void attn_mma_kernel(float* __restrict__ out) {
    extern __shared__ char smc[];
    const uint32_t smu = smem_to_u32(smc);
    const int tid  = threadIdx.x;
    const int wid  = tid >> 5;
    const int lane = tid & 31;

    const int qt   = 33 - blockIdx.x;
    const int hp   = blockIdx.y;
    const int head = hp * 2 + (wid >> 2);
    const int kvh  = hp >> 1;
    const int t0   = qt * 64;
    const int mrow = (wid & 3) * 16;

    const int r  = lane >> 2;
    const int cc = (lane & 3) * 2;

    int kts[12];
    int nkt = 0;
    if (t0 >= MMETA && qt >= 10) {
        kts[nkt++] = 0; kts[nkt++] = 1;
        for (int k = qt - 8; k <= qt; ++k) kts[nkt++] = k;
    } else {
        for (int k = 0; k <= qt; ++k) kts[nkt++] = k;
    }

    uint32_t qhi[8][4], qlo[8][4];
    {
        const float* qb = &g_qkv[(size_t)(t0 + mrow) * NQKV + head * HD];
#pragma unroll
        for (int ks = 0; ks < 8; ++ks) {
#pragma unroll
            for (int rg = 0; rg < 4; ++rg) {
                int row = r + (rg & 1) * 8;
                int col = ks * 16 + cc + (rg >> 1) * 8;
                float2 v = *(const float2*)&qb[(size_t)row * NQKV + col];
                uint32_t h = cvt_bf16x2(v.y, v.x);
                float f0 = __uint_as_float(h << 16);
                float f1 = __uint_as_float(h & 0xffff0000u);
                qhi[ks][rg] = h;
                qlo[ks][rg] = cvt_bf16x2(v.y - f1, v.x - f0);
            }
        }
    }

    const __nv_bfloat16* srcKV[4] = { g_Khi, g_Klo, g_Vhi, g_Vlo };
    auto issue = [&](int ti, int buf) {
        int s0 = kts[ti] * 64;
#pragma unroll
        for (int q = 0; q < 16; ++q) {
            int idx = q * 256 + tid;
            int arr = idx >> 10;
            int rem = idx & 1023;
            int row = rem >> 4;
            int ch  = rem & 15;
            const __nv_bfloat16* src = srcKV[arr] + (size_t)(s0 + row) * (NKV * HD) + kvh * HD + ch * 8;
            uint32_t dst = smu + buf * ASTAGE + arr * ARR_B + row * APITCH + ch * 16;
            cp_async16(dst, src);
        }
    };

    const uint32_t koff = (lane & 7) * APITCH + (lane >> 3) * 16;
    const uint32_t voff = ((lane & 7) + ((lane >> 3) & 1) * 8) * APITCH + ((lane >> 3) >> 1) * 16;

    float oacc[16][4];
#pragma unroll
    for (int j = 0; j < 16; ++j)
#pragma unroll
        for (int q = 0; q < 4; ++q) oacc[j][q] = 0.f;
    float m0 = -3.0e38f, m1 = -3.0e38f, l0 = 0.f, l1 = 0.f;

    const int tr0 = t0 + mrow + r;
    const int tr1 = tr0 + 8;

    issue(0, 0); CP_COMMIT();

    for (int it = 0; it < nkt; ++it) {
        if (it + 1 < nkt) issue(it + 1, (it + 1) & 1);
        CP_COMMIT();
        CP_WAIT1();
        __syncthreads();

        const uint32_t kb = smu + (it & 1) * ASTAGE;
        const uint32_t vb = kb + 2 * ARR_B;
        const int s0 = kts[it] * 64;

        float sacc[8][4];
#pragma unroll
        for (int j = 0; j < 8; ++j)
#pragma unroll
            for (int q = 0; q < 4; ++q) sacc[j][q] = 0.f;

#pragma unroll
        for (int j = 0; j < 8; ++j) {
            uint32_t jb = kb + j * (8 * APITCH) + koff;
#pragma unroll
            for (int k2 = 0; k2 < 4; ++k2) {
                uint32_t kh[4], kl[4];
                uint32_t a = jb + k2 * 64;
                ldsm_x4(kh, a);
                ldsm_x4(kl, a + ARR_B);
                mma_bf16(sacc[j], qhi[2 * k2], kh);
                mma_bf16(sacc[j], qhi[2 * k2], kl);
                mma_bf16(sacc[j], qlo[2 * k2], kh);
                mma_bf16(sacc[j], qhi[2 * k2 + 1], kh + 2);
                mma_bf16(sacc[j], qhi[2 * k2 + 1], kl + 2);
                mma_bf16(sacc[j], qlo[2 * k2 + 1], kh + 2);
            }
        }

#pragma unroll
        for (int j = 0; j < 8; ++j) {
            int sb0 = s0 + j * 8 + cc;
#pragma unroll
            for (int cx = 0; cx < 2; ++cx) {
                int s = sb0 + cx;
                bool v0 = (tr0 < MMETA) ? (s <= tr0)
                                        : ((s < MMETA) || ((s <= tr0) && (tr0 - s < WWIN)));
                bool v1 = (tr1 < MMETA) ? (s <= tr1)
                                        : ((s < MMETA) || ((s <= tr1) && (tr1 - s < WWIN)));
                if (!v0) sacc[j][cx]     = NEGV;
                if (!v1) sacc[j][cx + 2] = NEGV;
            }
        }

        float mx0 = NEGV, mx1 = NEGV;
#pragma unroll
        for (int j = 0; j < 8; ++j) {
            mx0 = fmaxf(mx0, fmaxf(sacc[j][0], sacc[j][1]));
            mx1 = fmaxf(mx1, fmaxf(sacc[j][2], sacc[j][3]));
        }
        mx0 = fmaxf(mx0, __shfl_xor_sync(0xffffffffu, mx0, 1));
        mx0 = fmaxf(mx0, __shfl_xor_sync(0xffffffffu, mx0, 2));
        mx1 = fmaxf(mx1, __shfl_xor_sync(0xffffffffu, mx1, 1));
        mx1 = fmaxf(mx1, __shfl_xor_sync(0xffffffffu, mx1, 2));

        float mn0 = fmaxf(m0, mx0);
        float mn1 = fmaxf(m1, mx1);
        float al0 = __expf(m0 - mn0);
        float al1 = __expf(m1 - mn1);
        m0 = mn0; m1 = mn1;

        float sum0 = 0.f, sum1 = 0.f;
#pragma unroll
        for (int j = 0; j < 8; ++j) {
            sacc[j][0] = __expf(sacc[j][0] - m0);
            sacc[j][1] = __expf(sacc[j][1] - m0);
            sacc[j][2] = __expf(sacc[j][2] - m1);
            sacc[j][3] = __expf(sacc[j][3] - m1);
            sum0 += sacc[j][0] + sacc[j][1];
            sum1 += sacc[j][2] + sacc[j][3];
        }
        sum0 += __shfl_xor_sync(0xffffffffu, sum0, 1);
        sum0 += __shfl_xor_sync(0xffffffffu, sum0, 2);
        sum1 += __shfl_xor_sync(0xffffffffu, sum1, 1);
        sum1 += __shfl_xor_sync(0xffffffffu, sum1, 2);
        l0 = l0 * al0 + sum0;
        l1 = l1 * al1 + sum1;

#pragma unroll
        for (int j = 0; j < 16; ++j) {
            oacc[j][0] *= al0; oacc[j][1] *= al0;
            oacc[j][2] *= al1; oacc[j][3] *= al1;
        }

#pragma unroll
        for (int kt = 0; kt < 4; ++kt) {
            uint32_t phi[4], plo[4];
#pragma unroll
            for (int hq = 0; hq < 2; ++hq) {
                const float* sj = sacc[2 * kt + hq];
                uint32_t h0 = cvt_bf16x2(sj[1], sj[0]);
                uint32_t h1 = cvt_bf16x2(sj[3], sj[2]);
                float a0 = __uint_as_float(h0 << 16);
                float a1 = __uint_as_float(h0 & 0xffff0000u);
                float b0 = __uint_as_float(h1 << 16);
                float b1 = __uint_as_float(h1 & 0xffff0000u);
                phi[2 * hq]     = h0;
                phi[2 * hq + 1] = h1;
                plo[2 * hq]     = cvt_bf16x2(sj[1] - a1, sj[0] - a0);
                plo[2 * hq + 1] = cvt_bf16x2(sj[3] - b1, sj[2] - b0);
            }
            uint32_t ktb = vb + kt * (16 * APITCH) + voff;
#pragma unroll
            for (int j2 = 0; j2 < 8; ++j2) {
                uint32_t vh[4], vl[4];
                uint32_t a = ktb + j2 * 32;
                ldsm_x4t(vh, a);
                ldsm_x4t(vl, a + ARR_B);
                mma_bf16(oacc[2 * j2], phi, vh);
                mma_bf16(oacc[2 * j2], phi, vl);
                mma_bf16(oacc[2 * j2], plo, vh);
                mma_bf16(oacc[2 * j2 + 1], phi, vh + 2);
                mma_bf16(oacc[2 * j2 + 1], phi, vl + 2);
                mma_bf16(oacc[2 * j2 + 1], plo, vh + 2);
            }
        }
        __syncthreads();
    }

    float inv0 = 1.0f / l0;
    float inv1 = 1.0f / l1;
    float* ob0 = &out[(size_t)tr0 * (NH * HD) + head * HD + cc];
    float* ob1 = &out[(size_t)tr1 * (NH * HD) + head * HD + cc];
#pragma unroll
    for (int j = 0; j < 16; ++j) {
        float2 v0 = { oacc[j][0] * inv0, oacc[j][1] * inv0 };
        float2 v1 = { oacc[j][2] * inv1, oacc[j][3] * inv1 };
        *(float2*)&ob0[j * 8] = v0;
        *(float2*)&ob1[j * 8] = v1;
    }
}

// ---------------------------------------------------------------------------
extern "C" void kernel_launch(void* const* d_in, const int* in_sizes, int n_in,
                              void* d_out, int out_size) {
    const float* hs   = (const float*)d_in[0];
    const float* w    = (const float*)d_in[1];
    const float* bias = (const float*)d_in[2];
    const int*   pos  = (const int*)d_in[3];
    float* out = (float*)d_out;

    init_invfreq_kernel<<<1, 64>>>();

    int na = T_TOK * HS / 4;
    split_a_kernel<<<(na + 255) / 256, 256>>>(hs);
    split_w_kernel<<<dim3(NQKV / 32, HS / 32), dim3(32, 8)>>>(w);

    cudaFuncSetAttribute(qkv_mma_kernel, cudaFuncAttributeMaxDynamicSharedMemorySize, GEMM_SMEM);
    qkv_mma_kernel<<<dim3(24, T_TOK / 64), 256, GEMM_SMEM>>>(bias, pos);

    cudaFuncSetAttribute(attn_mma_kernel, cudaFuncAttributeMaxDynamicSharedMemorySize, ATTN_SMEM);
    attn_mma_kernel<<<dim3(34, 8), 256, ATTN_SMEM>>>(out);
}

// round 6
// speedup vs baseline: 1.0893x; 1.0893x over previous
#include <cuda_runtime.h>
#include <cuda_bf16.h>
#include <cstdint>
#include <math.h>

#define T_TOK 2176
#define HS    2048
#define NQKV  3072
#define NH    16
#define NKV   4
#define HD    128
#define MMETA 128
#define WWIN  512
#define SCALE_F 0.08838834764831845f
#define NEGV  -1.0e30f

// ---------------------------------------------------------------------------
// scratch buffers
// ---------------------------------------------------------------------------
__device__ float g_qkv[T_TOK * NQKV];                    // Q roped+scaled fp32 (K/V cols unused)
__device__ __nv_bfloat16 g_Ahi[T_TOK * HS];
__device__ __nv_bfloat16 g_Alo[T_TOK * HS];
__device__ __nv_bfloat16 g_Bthi[NQKV * HS];              // W transposed [n][k]
__device__ __nv_bfloat16 g_Btlo[NQKV * HS];
__device__ __nv_bfloat16 g_Khi[T_TOK * NKV * HD];        // roped K split
__device__ __nv_bfloat16 g_Klo[T_TOK * NKV * HD];
__device__ __nv_bfloat16 g_Vhi[T_TOK * NKV * HD];
__device__ __nv_bfloat16 g_Vlo[T_TOK * NKV * HD];
__device__ float g_invfreq[64];

__device__ __forceinline__ uint32_t smem_to_u32(const void* p) {
    uint32_t a;
    asm("{ .reg .u64 t; cvta.to.shared.u64 t, %1; cvt.u32.u64 %0, t; }" : "=r"(a) : "l"(p));
    return a;
}
__device__ __forceinline__ uint32_t cvt_bf16x2(float hi, float lo) {
    uint32_t d;
    asm("cvt.rn.bf16x2.f32 %0, %1, %2;" : "=r"(d) : "f"(hi), "f"(lo));
    return d;
}
__device__ __forceinline__ void ldsm_x4(uint32_t* r, uint32_t addr) {
    asm volatile("ldmatrix.sync.aligned.m8n8.x4.shared.b16 {%0,%1,%2,%3}, [%4];"
                 : "=r"(r[0]), "=r"(r[1]), "=r"(r[2]), "=r"(r[3]) : "r"(addr));
}
__device__ __forceinline__ void ldsm_x4t(uint32_t* r, uint32_t addr) {
    asm volatile("ldmatrix.sync.aligned.m8n8.x4.trans.shared.b16 {%0,%1,%2,%3}, [%4];"
                 : "=r"(r[0]), "=r"(r[1]), "=r"(r[2]), "=r"(r[3]) : "r"(addr));
}
__device__ __forceinline__ void mma_bf16(float* c, const uint32_t* a, const uint32_t* b) {
    asm volatile(
        "mma.sync.aligned.m16n8k16.row.col.f32.bf16.bf16.f32 "
        "{%0,%1,%2,%3}, {%4,%5,%6,%7}, {%8,%9}, {%0,%1,%2,%3};"
        : "+f"(c[0]), "+f"(c[1]), "+f"(c[2]), "+f"(c[3])
        : "r"(a[0]), "r"(a[1]), "r"(a[2]), "r"(a[3]), "r"(b[0]), "r"(b[1]));
}
__device__ __forceinline__ void cp_async16(uint32_t dst, const void* src) {
    asm volatile("cp.async.ca.shared.global [%0], [%1], 16;" :: "r"(dst), "l"(src) : "memory");
}
#define CP_COMMIT() asm volatile("cp.async.commit_group;" ::: "memory")
#define CP_WAIT1()  asm volatile("cp.async.wait_group 1;" ::: "memory")
#define CP_WAIT0()  asm volatile("cp.async.wait_group 0;" ::: "memory")

// ---------------------------------------------------------------------------
// Stage -1: inv_freq table
// ---------------------------------------------------------------------------
__global__ void init_invfreq_kernel() {
    int i = threadIdx.x;
    g_invfreq[i] = (float)exp(-(double)(2 * i) * (1.0 / 128.0) * log(10000.0));
}

// ---------------------------------------------------------------------------
// Stage 0a: split hidden_states fp32 -> bf16 hi/lo
// ---------------------------------------------------------------------------
__global__ void split_a_kernel(const float* __restrict__ A) {
    int i = (blockIdx.x * blockDim.x + threadIdx.x) * 4;
    if (i >= T_TOK * HS) return;
    float4 v = *(const float4*)&A[i];
    __nv_bfloat16 h0 = __float2bfloat16(v.x);
    __nv_bfloat16 h1 = __float2bfloat16(v.y);
    __nv_bfloat16 h2 = __float2bfloat16(v.z);
    __nv_bfloat16 h3 = __float2bfloat16(v.w);
    __nv_bfloat162 hi01, hi23, lo01, lo23;
    hi01.x = h0; hi01.y = h1; hi23.x = h2; hi23.y = h3;
    lo01.x = __float2bfloat16(v.x - __bfloat162float(h0));
    lo01.y = __float2bfloat16(v.y - __bfloat162float(h1));
    lo23.x = __float2bfloat16(v.z - __bfloat162float(h2));
    lo23.y = __float2bfloat16(v.w - __bfloat162float(h3));
    *(__nv_bfloat162*)&g_Ahi[i]     = hi01;
    *(__nv_bfloat162*)&g_Ahi[i + 2] = hi23;
    *(__nv_bfloat162*)&g_Alo[i]     = lo01;
    *(__nv_bfloat162*)&g_Alo[i + 2] = lo23;
}

// ---------------------------------------------------------------------------
// Stage 0b: transpose + split W[2048,3072] -> Bt_hi/lo[3072][2048]
// ---------------------------------------------------------------------------
__global__ void split_w_kernel(const float* __restrict__ W) {
    __shared__ float tile[32][33];
    int n0 = blockIdx.x * 32;
    int k0 = blockIdx.y * 32;
    int tx = threadIdx.x;
    int ty = threadIdx.y;
#pragma unroll
    for (int p = 0; p < 4; ++p) {
        int k = ty + p * 8;
        tile[k][tx] = W[(size_t)(k0 + k) * NQKV + n0 + tx];
    }
    __syncthreads();
#pragma unroll
    for (int p = 0; p < 4; ++p) {
        int n = ty + p * 8;
        float v = tile[tx][n];
        __nv_bfloat16 hi = __float2bfloat16(v);
        __nv_bfloat16 lo = __float2bfloat16(v - __bfloat162float(hi));
        size_t o = (size_t)(n0 + n) * HS + k0 + tx;
        g_Bthi[o] = hi;
        g_Btlo[o] = lo;
    }
}

// ---------------------------------------------------------------------------
// Stage 1: bf16x3 GEMM (mma.sync), CTA 128x128 (one head-column x 128 tokens),
// 8 warps, warp tile 64x32, BK=32, 2-stage cp.async.
// Fused epilogue: bias + RoPE + Q-scale + K/V split via smem staging.
// Grid (24 heads, 17 token-tiles) = 408 CTAs.
// ---------------------------------------------------------------------------
#define BK 32
#define TILE_B (128 * 80)
#define STAGE_B (4 * TILE_B)
#define GEMM_SMEM (2 * STAGE_B)

__global__ __launch_bounds__(256, 2)
void qkv_mma_kernel(const float* __restrict__ bias, const int* __restrict__ pos) {
    extern __shared__ char smem[];
    const uint32_t sb = smem_to_u32(smem);
    const int tid  = threadIdx.x;
    const int wid  = tid >> 5;
    const int lane = tid & 31;
    const int head = blockIdx.x;            // 0..23
    const int bm = blockIdx.y * 128;
    const int bn = head * 128;
    const int wm = (wid >> 2) * 64;
    const int wn = (wid & 3) * 32;

    const __nv_bfloat16* srcs[4] = {
        g_Ahi + (size_t)bm * HS, g_Alo + (size_t)bm * HS,
        g_Bthi + (size_t)bn * HS, g_Btlo + (size_t)bn * HS };

    auto issue_stage = [&](int c, int s) {
#pragma unroll
        for (int q = 0; q < 8; ++q) {
            int idx = q * 256 + tid;
            int t   = idx >> 9;
            int cc  = idx & 511;
            int row = cc >> 2;
            int seg = cc & 3;
            const __nv_bfloat16* src = srcs[t] + (size_t)row * HS + c * BK + seg * 8;
            uint32_t dst = sb + s * STAGE_B + t * TILE_B + row * 80 + seg * 16;
            cp_async16(dst, src);
        }
    };

    float acc[4][4][4];
#pragma unroll
    for (int i = 0; i < 4; ++i)
#pragma unroll
        for (int j = 0; j < 4; ++j)
#pragma unroll
            for (int q = 0; q < 4; ++q) acc[i][j][q] = 0.f;

    issue_stage(0, 0); CP_COMMIT();
    issue_stage(1, 1); CP_COMMIT();

    const int arow  = wm + (lane & 15);
    const int acolh = (lane >> 4) << 3;
    // B x4 merge: lanes 0-15 -> n-tile j, lanes 16-31 -> n-tile j+1
    const int brow4 = (lane & 7) + ((lane >> 4) & 1) * 8;
    const int bcol4 = ((lane >> 3) & 1) * 8;

    const int NCH = HS / BK;   // 64
    for (int c = 0; c < NCH; ++c) {
        CP_WAIT1();
        __syncthreads();

        const uint32_t base = sb + (c & 1) * STAGE_B;

#pragma unroll
        for (int ks = 0; ks < 2; ++ks) {
            uint32_t ahi[4][4], alo[4][4];
#pragma unroll
            for (int i = 0; i < 4; ++i) {
                uint32_t aaddr = base + (arow + i * 16) * 80 + (acolh + ks * 16) * 2;
                ldsm_x4(ahi[i], aaddr);
                ldsm_x4(alo[i], aaddr + TILE_B);
            }
#pragma unroll
            for (int jp = 0; jp < 2; ++jp) {
                uint32_t bh[4], bl[4];
                uint32_t baddr = base + 2 * TILE_B +
                                 (wn + jp * 16 + brow4) * 80 + (bcol4 + ks * 16) * 2;
                ldsm_x4(bh, baddr);
                ldsm_x4(bl, baddr + TILE_B);
#pragma unroll
                for (int i = 0; i < 4; ++i) {
                    mma_bf16(acc[i][2 * jp], ahi[i], bh);
                    mma_bf16(acc[i][2 * jp], ahi[i], bl);
                    mma_bf16(acc[i][2 * jp], alo[i], bh);
                    mma_bf16(acc[i][2 * jp + 1], ahi[i], bh + 2);
                    mma_bf16(acc[i][2 * jp + 1], ahi[i], bl + 2);
                    mma_bf16(acc[i][2 * jp + 1], alo[i], bh + 2);
                }
            }
        }
        __syncthreads();
        if (c + 2 < NCH) issue_stage(c + 2, c & 1);
        CP_COMMIT();
    }

    // ---- fused epilogue: bias into smem staging tile ----
    CP_WAIT0();
    __syncthreads();
    float* Ct = (float*)smem;                 // [128][132] fp32 = 67584 B
    const int r  = lane >> 2;
    const int cc = (lane & 3) * 2;
#pragma unroll
    for (int i = 0; i < 4; ++i) {
#pragma unroll
        for (int j = 0; j < 4; ++j) {
            int col = wn + j * 8 + cc;
            float b0 = bias[bn + col], b1 = bias[bn + col + 1];
            int row = wm + i * 16 + r;
            Ct[row * 132 + col]           = acc[i][j][0] + b0;
            Ct[row * 132 + col + 1]       = acc[i][j][1] + b1;
            Ct[(row + 8) * 132 + col]     = acc[i][j][2] + b0;
            Ct[(row + 8) * 132 + col + 1] = acc[i][j][3] + b1;
        }
    }
    __syncthreads();

    // ---- rope / scale / split per head type (8192 pairs, 32 per thread) ----
#pragma unroll 4
    for (int p = 0; p < 32; ++p) {
        int idx = p * 256 + tid;
        int row = idx >> 6;
        int i   = idx & 63;
        int t   = bm + row;
        float x1 = Ct[row * 132 + i];
        float x2 = Ct[row * 132 + i + 64];
        if (head < 20) {
            float ang = (float)pos[t] * g_invfreq[i];
            float c = cosf(ang), s = sinf(ang);
            float y1 = x1 * c - x2 * s;
            float y2 = x2 * c + x1 * s;
            if (head < 16) {
                g_qkv[(size_t)t * NQKV + head * HD + i]      = y1 * SCALE_F;
                g_qkv[(size_t)t * NQKV + head * HD + i + 64] = y2 * SCALE_F;
            } else {
                size_t o = (size_t)t * (NKV * HD) + (head - 16) * HD + i;
                __nv_bfloat16 h1 = __float2bfloat16(y1);
                __nv_bfloat16 h2 = __float2bfloat16(y2);
                g_Khi[o]      = h1;
                g_Khi[o + 64] = h2;
                g_Klo[o]      = __float2bfloat16(y1 - __bfloat162float(h1));
                g_Klo[o + 64] = __float2bfloat16(y2 - __bfloat162float(h2));
            }
        } else {
            size_t o = (size_t)t * (NKV * HD) + (head - 20) * HD + i;
            __nv_bfloat16 h1 = __float2bfloat16(x1);
            __nv_bfloat16 h2 = __float2bfloat16(x2);
            g_Vhi[o]      = h1;
            g_Vhi[o + 64] = h2;
            g_Vlo[o]      = __float2bfloat16(x1 - __bfloat162float(h1));
            g_Vlo[o + 64] = __float2bfloat16(x2 - __bfloat162float(h2));
        }
    }
}

// ---------------------------------------------------------------------------
// Stage 3: attention via mma.sync, split precision, 2 heads per CTA.
// ---------------------------------------------------------------------------
#define APITCH 272
#define ARR_B  (64 * APITCH)
#define ASTAGE (4 * ARR_B)
#define ATTN_SMEM (2 * ASTAGE)

__device__ __forceinline__ void ldsm_x2(uint32_t* r, uint32_t addr) {
    asm volatile("ldmatrix.sync.aligned.m8n8.x2.shared.b16 {%0,%1}, [%2];"
                 : "=r"(r[0]), "=r"(r[1]) : "r"(addr));
}

__global__ __launch_bounds__(256, 1)
void attn_mma_kernel(float* __restrict__ out) {
    extern __shared__ char smc[];
    const uint32_t smu = smem_to_u32(smc);
    const int tid  = threadIdx.x;
    const int wid  = tid >> 5;
    const int lane = tid & 31;

    const int qt   = 33 - blockIdx.x;
    const int hp   = blockIdx.y;
    const int head = hp * 2 + (wid >> 2);
    const int kvh  = hp >> 1;
    const int t0   = qt * 64;
    const int mrow = (wid & 3) * 16;

    const int r  = lane >> 2;
    const int cc = (lane & 3) * 2;

    int kts[12];
    int nkt = 0;
    if (t0 >= MMETA && qt >= 10) {
        kts[nkt++] = 0; kts[nkt++] = 1;
        for (int k = qt - 8; k <= qt; ++k) kts[nkt++] = k;
    } else {
        for (int k = 0; k <= qt; ++k) kts[nkt++] = k;
    }

    uint32_t qhi[8][4], qlo[8][4];
    {
        const float* qb = &g_qkv[(size_t)(t0 + mrow) * NQKV + head * HD];
#pragma unroll
        for (int ks = 0; ks < 8; ++ks) {
#pragma unroll
            for (int rg = 0; rg < 4; ++rg) {
                int row = r + (rg & 1) * 8;
                int col = ks * 16 + cc + (rg >> 1) * 8;
                float2 v = *(const float2*)&qb[(size_t)row * NQKV + col];
                uint32_t h = cvt_bf16x2(v.y, v.x);
                float f0 = __uint_as_float(h << 16);
                float f1 = __uint_as_float(h & 0xffff0000u);
                qhi[ks][rg] = h;
                qlo[ks][rg] = cvt_bf16x2(v.y - f1, v.x - f0);
            }
        }
    }

    const __nv_bfloat16* srcKV[4] = { g_Khi, g_Klo, g_Vhi, g_Vlo };
    auto issue = [&](int ti, int buf) {
        int s0 = kts[ti] * 64;
#pragma unroll
        for (int q = 0; q < 16; ++q) {
            int idx = q * 256 + tid;
            int arr = idx >> 10;
            int rem = idx & 1023;
            int row = rem >> 4;
            int ch  = rem & 15;
            const __nv_bfloat16* src = srcKV[arr] + (size_t)(s0 + row) * (NKV * HD) + kvh * HD + ch * 8;
            uint32_t dst = smu + buf * ASTAGE + arr * ARR_B + row * APITCH + ch * 16;
            cp_async16(dst, src);
        }
    };

    const uint32_t koff = (lane & 7) * APITCH + (lane >> 3) * 16;
    const uint32_t voff = ((lane & 7) + ((lane >> 3) & 1) * 8) * APITCH + ((lane >> 3) >> 1) * 16;

    float oacc[16][4];
#pragma unroll
    for (int j = 0; j < 16; ++j)
#pragma unroll
        for (int q = 0; q < 4; ++q) oacc[j][q] = 0.f;
    float m0 = -3.0e38f, m1 = -3.0e38f, l0 = 0.f, l1 = 0.f;

    const int tr0 = t0 + mrow + r;
    const int tr1 = tr0 + 8;

    issue(0, 0); CP_COMMIT();

    for (int it = 0; it < nkt; ++it) {
        if (it + 1 < nkt) issue(it + 1, (it + 1) & 1);
        CP_COMMIT();
        CP_WAIT1();
        __syncthreads();

        const uint32_t kb = smu + (it & 1) * ASTAGE;
        const uint32_t vb = kb + 2 * ARR_B;
        const int s0 = kts[it] * 64;

        float sacc[8][4];
#pragma unroll
        for (int j = 0; j < 8; ++j)
#pragma unroll
            for (int q = 0; q < 4; ++q) sacc[j][q] = 0.f;

#pragma unroll
        for (int j = 0; j < 8; ++j) {
            uint32_t jb = kb + j * (8 * APITCH) + koff;
#pragma unroll
            for (int k2 = 0; k2 < 4; ++k2) {
                uint32_t kh[4], kl[4];
                uint32_t a = jb + k2 * 64;
                ldsm_x4(kh, a);
                ldsm_x4(kl, a + ARR_B);
                mma_bf16(sacc[j], qhi[2 * k2], kh);
                mma_bf16(sacc[j], qhi[2 * k2], kl);
                mma_bf16(sacc[j], qlo[2 * k2], kh);
                mma_bf16(sacc[j], qhi[2 * k2 + 1], kh + 2);
                mma_bf16(sacc[j], qhi[2 * k2 + 1], kl + 2);
                mma_bf16(sacc[j], qlo[2 * k2 + 1], kh + 2);
            }
        }

#pragma unroll
        for (int j = 0; j < 8; ++j) {
            int sb0 = s0 + j * 8 + cc;
#pragma unroll
            for (int cx = 0; cx < 2; ++cx) {
                int s = sb0 + cx;
                bool v0 = (tr0 < MMETA) ? (s <= tr0)
                                        : ((s < MMETA) || ((s <= tr0) && (tr0 - s < WWIN)));
                bool v1 = (tr1 < MMETA) ? (s <= tr1)
                                        : ((s < MMETA) || ((s <= tr1) && (tr1 - s < WWIN)));
                if (!v0) sacc[j][cx]     = NEGV;
                if (!v1) sacc[j][cx + 2] = NEGV;
            }
        }

        float mx0 = NEGV, mx1 = NEGV;
#pragma unroll
        for (int j = 0; j < 8; ++j) {
            mx0 = fmaxf(mx0, fmaxf(sacc[j][0], sacc[j][1]));
            mx1 = fmaxf(mx1, fmaxf(sacc[j][2], sacc[j][3]));
        }
        mx0 = fmaxf(mx0, __shfl_xor_sync(0xffffffffu, mx0, 1));
        mx0 = fmaxf(mx0, __shfl_xor_sync(0xffffffffu, mx0, 2));
        mx1 = fmaxf(mx1, __shfl_xor_sync(0xffffffffu, mx1, 1));
        mx1 = fmaxf(mx1, __shfl_xor_sync(0xffffffffu, mx1, 2));

        float mn0 = fmaxf(m0, mx0);
        float mn1 = fmaxf(m1, mx1);
        float al0 = __expf(m0 - mn0);
        float al1 = __expf(m1 - mn1);
        m0 = mn0; m1 = mn1;

        float sum0 = 0.f, sum1 = 0.f;
#pragma unroll
        for (int j = 0; j < 8; ++j) {
            sacc[j][0] = __expf(sacc[j][0] - m0);
            sacc[j][1] = __expf(sacc[j][1] - m0);
            sacc[j][2] = __expf(sacc[j][2] - m1);
            sacc[j][3] = __expf(sacc[j][3] - m1);
            sum0 += sacc[j][0] + sacc[j][1];
            sum1 += sacc[j][2] + sacc[j][3];
        }
        sum0 += __shfl_xor_sync(0xffffffffu, sum0, 1);
        sum0 += __shfl_xor_sync(0xffffffffu, sum0, 2);
        sum1 += __shfl_xor_sync(0xffffffffu, sum1, 1);
        sum1 += __shfl_xor_sync(0xffffffffu, sum1, 2);
        l0 = l0 * al0 + sum0;
        l1 = l1 * al1 + sum1;

#pragma unroll
        for (int j = 0; j < 16; ++j) {
            oacc[j][0] *= al0; oacc[j][1] *= al0;
            oacc[j][2] *= al1; oacc[j][3] *= al1;
        }

#pragma unroll
        for (int kt = 0; kt < 4; ++kt) {
            uint32_t phi[4], plo[4];
#pragma unroll
            for (int hq = 0; hq < 2; ++hq) {
                const float* sj = sacc[2 * kt + hq];
                uint32_t h0 = cvt_bf16x2(sj[1], sj[0]);
                uint32_t h1 = cvt_bf16x2(sj[3], sj[2]);
                float a0 = __uint_as_float(h0 << 16);
                float a1 = __uint_as_float(h0 & 0xffff0000u);
                float b0 = __uint_as_float(h1 << 16);
                float b1 = __uint_as_float(h1 & 0xffff0000u);
                phi[2 * hq]     = h0;
                phi[2 * hq + 1] = h1;
                plo[2 * hq]     = cvt_bf16x2(sj[1] - a1, sj[0] - a0);
                plo[2 * hq + 1] = cvt_bf16x2(sj[3] - b1, sj[2] - b0);
            }
            uint32_t ktb = vb + kt * (16 * APITCH) + voff;
#pragma unroll
            for (int j2 = 0; j2 < 8; ++j2) {
                uint32_t vh[4], vl[4];
                uint32_t a = ktb + j2 * 32;
                ldsm_x4t(vh, a);
                ldsm_x4t(vl, a + ARR_B);
                mma_bf16(oacc[2 * j2], phi, vh);
                mma_bf16(oacc[2 * j2], phi, vl);
                mma_bf16(oacc[2 * j2], plo, vh);
                mma_bf16(oacc[2 * j2 + 1], phi, vh + 2);
                mma_bf16(oacc[2 * j2 + 1], phi, vl + 2);
                mma_bf16(oacc[2 * j2 + 1], plo, vh + 2);
            }
        }
        __syncthreads();
    }

    float inv0 = 1.0f / l0;
    float inv1 = 1.0f / l1;
    float* ob0 = &out[(size_t)tr0 * (NH * HD) + head * HD + cc];
    float* ob1 = &out[(size_t)tr1 * (NH * HD) + head * HD + cc];
#pragma unroll
    for (int j = 0; j < 16; ++j) {
        float2 v0 = { oacc[j][0] * inv0, oacc[j][1] * inv0 };
        float2 v1 = { oacc[j][2] * inv1, oacc[j][3] * inv1 };
        *(float2*)&ob0[j * 8] = v0;
        *(float2*)&ob1[j * 8] = v1;
    }
}

// ---------------------------------------------------------------------------
extern "C" void kernel_launch(void* const* d_in, const int* in_sizes, int n_in,
                              void* d_out, int out_size) {
    const float* hs   = (const float*)d_in[0];
    const float* w    = (const float*)d_in[1];
    const float* bias = (const float*)d_in[2];
    const int*   pos  = (const int*)d_in[3];
    float* out = (float*)d_out;

    init_invfreq_kernel<<<1, 64>>>();

    int na = T_TOK * HS / 4;
    split_a_kernel<<<(na + 255) / 256, 256>>>(hs);
    split_w_kernel<<<dim3(NQKV / 32, HS / 32), dim3(32, 8)>>>(w);

    cudaFuncSetAttribute(qkv_mma_kernel, cudaFuncAttributeMaxDynamicSharedMemorySize, GEMM_SMEM);
    qkv_mma_kernel<<<dim3(24, T_TOK / 128), 256, GEMM_SMEM>>>(bias, pos);

    cudaFuncSetAttribute(attn_mma_kernel, cudaFuncAttributeMaxDynamicSharedMemorySize, ATTN_SMEM);
    attn_mma_kernel<<<dim3(34, 8), 256, ATTN_SMEM>>>(out);
}